// round 8
// baseline (speedup 1.0000x reference)
#include <cuda_runtime.h>
#include <cuda_fp16.h>
#include <cstdint>

// Problem constants
#define NB 2
#define NS 2048
#define ND 1024
#define NH 16
#define NDH 64
#define NM (NB * NS)

// Scratch (device globals: allocation-free)
__device__ __half g_q[(size_t)NB * NH * NS * NDH];     // [b,h,s,dh]
__device__ __half g_k[(size_t)NB * NH * NS * NDH];     // [b,h,s,dh]
__device__ __half g_v[(size_t)NB * NH * NS * NDH];     // [b,h,dh,s]  TRANSPOSED
__device__ float  g_attn[(size_t)NB * NS * ND];
__device__ float  g_rowsum[(size_t)NB * NH * NS];

// ---------------- helpers ----------------
__device__ __forceinline__ uint32_t f2h2(float a, float b) {
    __half2 h = __floats2half2_rn(a, b);
    return *reinterpret_cast<uint32_t*>(&h);
}

// D(16x8,f32) += A(16x16,f16) * B(16x8,f16)
__device__ __forceinline__ void mma_f16(float c[4], const uint32_t a[4], const uint32_t b[2]) {
    asm volatile(
        "mma.sync.aligned.m16n8k16.row.col.f32.f16.f16.f32 "
        "{%0,%1,%2,%3}, {%4,%5,%6,%7}, {%8,%9}, {%0,%1,%2,%3};"
        : "+f"(c[0]), "+f"(c[1]), "+f"(c[2]), "+f"(c[3])
        : "r"(a[0]), "r"(a[1]), "r"(a[2]), "r"(a[3]), "r"(b[0]), "r"(b[1]));
}

__device__ __forceinline__ void ldm_x4(uint32_t* r, const uint32_t* p) {
    uint32_t a = (uint32_t)__cvta_generic_to_shared(p);
    asm volatile("ldmatrix.sync.aligned.m8n8.x4.shared.b16 {%0,%1,%2,%3}, [%4];"
        : "=r"(r[0]), "=r"(r[1]), "=r"(r[2]), "=r"(r[3]) : "r"(a));
}
__device__ __forceinline__ void ldm_x2(uint32_t* r, const uint32_t* p) {
    uint32_t a = (uint32_t)__cvta_generic_to_shared(p);
    asm volatile("ldmatrix.sync.aligned.m8n8.x2.shared.b16 {%0,%1}, [%2];"
        : "=r"(r[0]), "=r"(r[1]) : "r"(a));
}

__device__ __forceinline__ void cpa16(void* smem, const void* g) {
    uint32_t s = (uint32_t)__cvta_generic_to_shared(smem);
    asm volatile("cp.async.cg.shared.global [%0], [%1], 16;" :: "r"(s), "l"(g));
}
__device__ __forceinline__ void cpa_commit() { asm volatile("cp.async.commit_group;"); }
__device__ __forceinline__ void cpa_wait0() { asm volatile("cp.async.wait_group 0;" ::: "memory"); }
__device__ __forceinline__ void cpa_wait1() { asm volatile("cp.async.wait_group 1;" ::: "memory"); }

// ---------------------------------------------------------------------------
// GEMM: C = A(f32, MxK) @ W^T(f32, NxK) + bias, fp16 tensor cores, f32 accum.
// Fragments via ldmatrix (x4 for A, x2 for B). BM=BN=128, BK=32, 256 threads.
// MODE 0: f32 row-major out. MODE 1: half out [b,h,s,dh]. MODE 2: half out
// [b,h,dh,s] (transposed, for V).
// ---------------------------------------------------------------------------
template <int MODE>
__global__ __launch_bounds__(256) void gemm_f16(
    const float* __restrict__ A, const float* __restrict__ W,
    const float* __restrict__ bias, void* __restrict__ outv)
{
    __shared__ uint32_t As[128 * 20];
    __shared__ uint32_t Ws[128 * 20];

    const int tid = threadIdx.x;
    const int wid = tid >> 5, lane = tid & 31;
    const int g = lane >> 2, t = lane & 3;
    const int wm = (wid & 3) * 32;
    const int wn = (wid >> 2) * 64;
    const int bm = blockIdx.y * 128, bn = blockIdx.x * 128;

    const int lr = tid >> 1;            // staging row 0..127
    const int lp = (tid & 1) * 8;       // pair offset 0/8

    // ldmatrix lane-address components
    const int la16 = lane & 15;                 // A: row within 16
    const int lac  = (lane >> 4) * 4;           // A: chunk col (0/4)
    const int lb8  = lane & 7;                  // B: row within 8
    const int lbc  = ((lane >> 3) & 1) * 4;     // B: chunk col (0/4)

    float c[2][8][4];
#pragma unroll
    for (int i = 0; i < 2; i++)
#pragma unroll
        for (int j = 0; j < 8; j++)
#pragma unroll
            for (int q = 0; q < 4; q++) c[i][j][q] = 0.f;

    const float* aptr = A + (size_t)(bm + lr) * ND + lp * 2;
    const float* wptr = W + (size_t)(bn + lr) * ND + lp * 2;

    for (int k0 = 0; k0 < ND; k0 += 32) {
        float4 a0 = *(const float4*)(aptr + k0);
        float4 a1 = *(const float4*)(aptr + k0 + 4);
        float4 a2 = *(const float4*)(aptr + k0 + 8);
        float4 a3 = *(const float4*)(aptr + k0 + 12);
        float4 w0 = *(const float4*)(wptr + k0);
        float4 w1 = *(const float4*)(wptr + k0 + 4);
        float4 w2 = *(const float4*)(wptr + k0 + 8);
        float4 w3 = *(const float4*)(wptr + k0 + 12);
        __syncthreads();
        *(uint4*)&As[lr * 20 + lp] =
            make_uint4(f2h2(a0.x, a0.y), f2h2(a0.z, a0.w), f2h2(a1.x, a1.y), f2h2(a1.z, a1.w));
        *(uint4*)&As[lr * 20 + lp + 4] =
            make_uint4(f2h2(a2.x, a2.y), f2h2(a2.z, a2.w), f2h2(a3.x, a3.y), f2h2(a3.z, a3.w));
        *(uint4*)&Ws[lr * 20 + lp] =
            make_uint4(f2h2(w0.x, w0.y), f2h2(w0.z, w0.w), f2h2(w1.x, w1.y), f2h2(w1.z, w1.w));
        *(uint4*)&Ws[lr * 20 + lp + 4] =
            make_uint4(f2h2(w2.x, w2.y), f2h2(w2.z, w2.w), f2h2(w3.x, w3.y), f2h2(w3.z, w3.w));
        __syncthreads();

#pragma unroll
        for (int ch = 0; ch < 2; ch++) {     // two k16 chunks per BK=32
            uint32_t af[2][4];
            ldm_x4(af[0], &As[(wm + la16)      * 20 + ch * 8 + lac]);
            ldm_x4(af[1], &As[(wm + 16 + la16) * 20 + ch * 8 + lac]);
#pragma unroll
            for (int nt = 0; nt < 8; nt++) {
                uint32_t bf[2];
                ldm_x2(bf, &Ws[(wn + nt * 8 + lb8) * 20 + ch * 8 + lbc]);
                mma_f16(c[0][nt], af[0], bf);
                mma_f16(c[1][nt], af[1], bf);
            }
        }
    }

#pragma unroll
    for (int mt = 0; mt < 2; mt++) {
#pragma unroll
        for (int rr = 0; rr < 2; rr++) {
            const int m = bm + wm + mt * 16 + g + rr * 8;
            const int b = m >> 11, sIdx = m & (NS - 1);
#pragma unroll
            for (int nt = 0; nt < 8; nt++) {
                const int col = bn + wn + nt * 8 + 2 * t;
                const float vx = c[mt][nt][rr * 2 + 0] + bias[col];
                const float vy = c[mt][nt][rr * 2 + 1] + bias[col + 1];
                if (MODE == 0) {
                    *(float2*)&((float*)outv)[(size_t)m * ND + col] = make_float2(vx, vy);
                } else if (MODE == 1) {
                    const int h = col >> 6, dh = col & 63;
                    *(uint32_t*)&((__half*)outv)[((size_t)(b * NH + h) * NS + sIdx) * NDH + dh] =
                        f2h2(vx, vy);
                } else {
                    const int h = col >> 6, dh = col & 63;
                    __half* o = (__half*)outv + ((size_t)(b * NH + h) * NDH) * NS;
                    o[(size_t)dh * NS + sIdx]       = __float2half_rn(vx);
                    o[(size_t)(dh + 1) * NS + sIdx] = __float2half_rn(vy);
                }
            }
        }
    }
}

// ---------------------------------------------------------------------------
// Attention v8 (fp16 + ldmatrix): v7 structure, all fragments via ldmatrix.
// Block = 64 q rows, 256 threads (8 warps: 4m x 2n). Warp tile 16q x 32k.
// K tiles [key][32 pairs], V tiles [dh][32 key-pairs]. Row stride 36 words.
// cp.async double-buffered K/V; separate E buffer; 3 syncs/tile.
// ---------------------------------------------------------------------------
#define NT_TILES (NS / 64)
#define KST 36
__global__ __launch_bounds__(256) void attn_f16(
    const int* __restrict__ mask, float* __restrict__ wout)
{
    extern __shared__ uint32_t dsm[];
    uint32_t* KsB = dsm;                       // 2 x 64*36
    uint32_t* VsB = dsm + 2 * 64 * KST;        // 2 x 64*36
    uint32_t* Es  = VsB + 2 * 64 * KST;        // 64*36
    float*    red = (float*)(Es + 64 * KST);   // 128 floats

    const int b = blockIdx.z, h = blockIdx.y;
    const int q0 = blockIdx.x * 64;
    const int tid = threadIdx.x;
    const int wid = tid >> 5, lane = tid & 31;
    const int g = lane >> 2, t = lane & 3;
    const int wm = (wid & 3) * 16;             // q rows within block
    const int wn = (wid >> 2) * 32;            // key cols (S) / dh cols (PV)
    const size_t bh = (size_t)(b * NH + h);

    // ldmatrix lane-address components
    const int la16 = lane & 15;                // A: row within 16
    const int lac  = (lane >> 4) * 4;          // A: chunk col (0/4)
    const int lb8  = lane & 7;                 // B: row within 8
    const int lbc  = (lane >> 3) * 4;          // B: chunk col (0/4/8/12)

    // Staging coords: 64 rows x 8 chunks(16B); thread does chunks c and c+4
    const int sr = tid >> 2;                   // row 0..63
    const int sch = tid & 3;                   // chunk 0..3

    // Stage Q (half, 64x64) into Es
    const __half* qptr = g_q + (bh * NS + q0) * NDH;
    cpa16(&Es[sr * KST + sch * 4],      qptr + sr * NDH + sch * 8);
    cpa16(&Es[sr * KST + sch * 4 + 16], qptr + sr * NDH + sch * 8 + 32);
    cpa_commit();
    cpa_wait0();
    __syncthreads();

    // Q fragments: 4 k16-chunks x 4 regs via ldmatrix.x4
    uint32_t qf[4][4];
#pragma unroll
    for (int ch = 0; ch < 4; ch++)
        ldm_x4(qf[ch], &Es[(wm + la16) * KST + ch * 8 + lac]);
    __syncthreads();   // qf built before Es is reused for E

    float cacc[4][4];
#pragma unroll
    for (int nt = 0; nt < 4; nt++)
#pragma unroll
        for (int q = 0; q < 4; q++) cacc[nt][q] = 0.f;
    float rs0 = 0.f, rs1 = 0.f;

    const int* mbase = mask + (size_t)b * NS * NS;
    float* wbase = wout ? wout + bh * NS * NS : nullptr;
    const __half* kbase = g_k + bh * NS * NDH;         // [s][dh]
    const __half* vbase = g_v + bh * (size_t)NDH * NS; // [dh][s]

    // Prologue: tile 0 into buffer 0. K rows = keys; V rows = dh.
    cpa16(&KsB[sr * KST + sch * 4],      kbase + sr * NDH + sch * 8);
    cpa16(&KsB[sr * KST + sch * 4 + 16], kbase + sr * NDH + sch * 8 + 32);
    cpa16(&VsB[sr * KST + sch * 4],      vbase + (size_t)sr * NS + sch * 8);
    cpa16(&VsB[sr * KST + sch * 4 + 16], vbase + (size_t)sr * NS + sch * 8 + 32);
    cpa_commit();

    for (int kt = 0; kt < NT_TILES; kt++) {
        if (kt + 1 < NT_TILES) {
            const int nb = (kt + 1) & 1;
            const __half* kp = kbase + (size_t)(kt + 1) * 64 * NDH;
            const __half* vp = vbase + (size_t)(kt + 1) * 64;   // col offset in [dh][s]
            uint32_t* kd = KsB + nb * 64 * KST;
            uint32_t* vd = VsB + nb * 64 * KST;
            cpa16(&kd[sr * KST + sch * 4],      kp + sr * NDH + sch * 8);
            cpa16(&kd[sr * KST + sch * 4 + 16], kp + sr * NDH + sch * 8 + 32);
            cpa16(&vd[sr * KST + sch * 4],      vp + (size_t)sr * NS + sch * 8);
            cpa16(&vd[sr * KST + sch * 4 + 16], vp + (size_t)sr * NS + sch * 8 + 32);
            cpa_commit();
            cpa_wait1();
        } else {
            cpa_wait0();
        }
        __syncthreads();

        const uint32_t* Ks = KsB + (kt & 1) * 64 * KST;
        const uint32_t* Vs = VsB + (kt & 1) * 64 * KST;

        // S phase: preload all K fragments (8 ldmatrix), then 16 mma
        uint32_t kb[4][8];
#pragma unroll
        for (int nt = 0; nt < 4; nt++) {
            const uint32_t* kp = &Ks[(wn + nt * 8 + lb8) * KST + lbc];
            ldm_x4(&kb[nt][0], kp);        // bf pairs for ch0, ch1
            ldm_x4(&kb[nt][4], kp + 16);   // bf pairs for ch2, ch3
        }
        float lg[4][4];
#pragma unroll
        for (int nt = 0; nt < 4; nt++)
#pragma unroll
            for (int q = 0; q < 4; q++) lg[nt][q] = 0.f;
#pragma unroll
        for (int ch = 0; ch < 4; ch++)
#pragma unroll
            for (int nt = 0; nt < 4; nt++)
                mma_f16(lg[nt], qf[ch], &kb[nt][ch * 2]);

        // mask + exp + unnormalized weight write + rowsum; E -> Es (half2)
        const int qr0 = q0 + wm + g, qr1 = qr0 + 8;
#pragma unroll
        for (int nt = 0; nt < 4; nt++) {
            const int klocal = wn + nt * 8 + 2 * t;
            const int kcg = kt * 64 + klocal;
            int2 m0 = *(const int2*)(mbase + (size_t)qr0 * NS + kcg);
            int2 m1 = *(const int2*)(mbase + (size_t)qr1 * NS + kcg);
            float e0 = m0.x ? 0.f : __expf(lg[nt][0] * 0.125f);
            float e1 = m0.y ? 0.f : __expf(lg[nt][1] * 0.125f);
            float e2 = m1.x ? 0.f : __expf(lg[nt][2] * 0.125f);
            float e3 = m1.y ? 0.f : __expf(lg[nt][3] * 0.125f);
            rs0 += e0 + e1;
            rs1 += e2 + e3;
            if (wbase) {
                *(float2*)&wbase[(size_t)qr0 * NS + kcg] = make_float2(e0, e1);
                *(float2*)&wbase[(size_t)qr1 * NS + kcg] = make_float2(e2, e3);
            }
            const int pair = (klocal >> 1);
            Es[(wm + g)     * KST + pair] = f2h2(e0, e1);
            Es[(wm + g + 8) * KST + pair] = f2h2(e2, e3);
        }
        __syncthreads();   // all E tiles visible

        // PV: af (E) via 4 ldmatrix.x4, V fragments via 8 ldmatrix.x4
        uint32_t af[4][4];
#pragma unroll
        for (int ch = 0; ch < 4; ch++)
            ldm_x4(af[ch], &Es[(wm + la16) * KST + ch * 8 + lac]);
#pragma unroll
        for (int nt = 0; nt < 4; nt++) {
            uint32_t vb[8];
            const uint32_t* vp = &Vs[(wn + nt * 8 + lb8) * KST + lbc];
            ldm_x4(&vb[0], vp);
            ldm_x4(&vb[4], vp + 16);
#pragma unroll
            for (int ch = 0; ch < 4; ch++)
                mma_f16(cacc[nt], af[ch], &vb[ch * 2]);
        }
        __syncthreads();   // compute done before buffers/Es overwritten
    }

    // Rowsums: quad-reduce over t, combine the two n-warps via smem
    rs0 += __shfl_xor_sync(0xffffffffu, rs0, 1);
    rs0 += __shfl_xor_sync(0xffffffffu, rs0, 2);
    rs1 += __shfl_xor_sync(0xffffffffu, rs1, 1);
    rs1 += __shfl_xor_sync(0xffffffffu, rs1, 2);
    if (t == 0) {
        const int half = (wid >= 4) ? 64 : 0;
        red[half + wm + g]     = rs0;
        red[half + wm + g + 8] = rs1;
    }
    __syncthreads();
    const float tot0 = red[wm + g]     + red[64 + wm + g];
    const float tot1 = red[wm + g + 8] + red[64 + wm + g + 8];
    if (wid < 4 && t == 0) {
        g_rowsum[bh * NS + q0 + wm + g]     = tot0;
        g_rowsum[bh * NS + q0 + wm + g + 8] = tot1;
    }
    const float inv0 = 1.f / tot0, inv1 = 1.f / tot1;

    // Normalized attn, concat layout (b, s, h*64 + dh), f32
    const int q = q0 + wm + g;
#pragma unroll
    for (int nt = 0; nt < 4; nt++) {
        const int dh = wn + nt * 8 + 2 * t;
        *(float2*)&g_attn[((size_t)b * NS + q) * ND + h * NDH + dh] =
            make_float2(cacc[nt][0] * inv0, cacc[nt][1] * inv0);
        *(float2*)&g_attn[((size_t)b * NS + q + 8) * ND + h * NDH + dh] =
            make_float2(cacc[nt][2] * inv1, cacc[nt][3] * inv1);
    }
}

// Scale each weights row by 1/rowsum
__global__ __launch_bounds__(128) void norm_w(float* __restrict__ w)
{
    const int row = blockIdx.x;
    const float inv = 1.f / g_rowsum[row];
    float4* p = (float4*)(w + (size_t)row * NS);
#pragma unroll
    for (int i = threadIdx.x; i < NS / 4; i += 128) {
        float4 v = p[i];
        v.x *= inv; v.y *= inv; v.z *= inv; v.w *= inv;
        p[i] = v;
    }
}

extern "C" void kernel_launch(void* const* d_in, const int* in_sizes, int n_in,
                              void* d_out, int out_size)
{
    const float* Xq  = (const float*)d_in[0];
    const float* Xk  = (const float*)d_in[1];
    const float* Xv  = (const float*)d_in[2];
    const int*   msk = (const int*)d_in[3];
    const float* Wq  = (const float*)d_in[4];
    const float* bq  = (const float*)d_in[5];
    const float* Wk  = (const float*)d_in[6];
    const float* bk  = (const float*)d_in[7];
    const float* Wv  = (const float*)d_in[8];
    const float* bv  = (const float*)d_in[9];
    const float* Wo  = (const float*)d_in[10];
    const float* bo  = (const float*)d_in[11];

    float* out = (float*)d_out;
    const size_t n_attn = (size_t)NB * NS * ND;
    const size_t n_w    = (size_t)NB * NH * NS * NS;

    float* attn_dst = nullptr;
    float* w_dst = nullptr;
    if ((size_t)out_size >= n_attn + n_w) { attn_dst = out; w_dst = out + n_attn; }
    else if ((size_t)out_size >= n_w)     { w_dst = out; }
    else                                  { attn_dst = out; }

    __half *pq, *pk, *pv;
    float *pa;
    cudaGetSymbolAddress((void**)&pq, g_q);
    cudaGetSymbolAddress((void**)&pk, g_k);
    cudaGetSymbolAddress((void**)&pv, g_v);
    cudaGetSymbolAddress((void**)&pa, g_attn);

    dim3 ggrid(ND / 128, NM / 128);   // (8, 32)
    gemm_f16<1><<<ggrid, 256>>>(Xq, Wq, bq, pq);
    gemm_f16<1><<<ggrid, 256>>>(Xk, Wk, bk, pk);
    gemm_f16<2><<<ggrid, 256>>>(Xv, Wv, bv, pv);   // V transposed [b,h,dh,s]

    const int attn_smem = (5 * 64 * KST) * 4 + 128 * 4 + 256;  // ~46.8 KB
    cudaFuncSetAttribute(attn_f16, cudaFuncAttributeMaxDynamicSharedMemorySize, attn_smem);
    attn_f16<<<dim3(NS / 64, NH, NB), 256, attn_smem>>>(msk, w_dst);

    if (w_dst) norm_w<<<NB * NH * NS, 128>>>(w_dst);

    if (attn_dst) gemm_f16<0><<<ggrid, 256>>>(pa, Wo, bo, attn_dst);
}